// round 16
// baseline (speedup 1.0000x reference)
#include <cuda_runtime.h>

#define N_COL 256
#define N_ROW 256
#define N_CELLS (N_COL * N_ROW)
#define N_WORDS (N_CELLS / 32)          // 2048 bitmask words (8 KB)
#define N_AGENT_PTS (64 * 1001)         // 64064
#define N_PTS4 (N_AGENT_PTS / 4)        // 16016
#define BATCH 512
#define N_M4 (N_CELLS / 4)              // 16384 float4s per batch row
#define BPT 4                           // batch rows per apply thread (measured optimum)

#define SCAT_BLOCKS 63                  // ceil(16016/256)
#define APPLY_BLOCKS (N_M4 * (BATCH / BPT) / 256)   // 8192

// Parity double-buffered bitmask + counts. Call with epoch e uses buffer
// e&1, zeroed during call e-1's apply (kernel boundary publishes it).
// Zero-initialized at module load -> epoch 0 valid.
__device__ __align__(16) unsigned int g_mask[2][N_WORDS];
__device__ unsigned int g_cnt[2];
__device__ unsigned int g_par_pub;      // parity of the current call
// Monotonic scatter call counter (never reset -> graph-replay deterministic).
__device__ unsigned int g_scat_calls;

__device__ __forceinline__ bool mark_point(float x, float y, unsigned int par) {
    float fx = x * (float)N_COL;
    float fy = y * (float)N_ROW;
    float cx = floorf(fx);
    float cy = floorf(fy);
    float rx = fx - cx;
    float ry = fy - cy;
    bool in_box = (rx >= 0.25f) && (rx <= 0.75f) &&
                  (ry >= 0.25f) && (ry <= 0.75f);
    if (!in_box) return false;
    int ix = min(max((int)cx, 0), N_COL - 1);
    int iy = min(max((int)cy, 0), N_ROW - 1);
    // rot90 CCW folded in: (ix,iy) -> k = (255-iy)*256 + ix
    int k = (N_ROW - 1 - iy) * N_COL + ix;
    unsigned int bit = 1u << (k & 31);
    unsigned int old = atomicOr(&g_mask[par][k >> 5], bit);
    return !(old & bit);                // first toucher this call
}

// Scatter: 63 blocks, 4 agent points per thread via float4 loads.
// No init phase, no barrier — buffer pre-zeroed by previous apply.
__global__ void __launch_bounds__(256)
k_scatter(const float4* __restrict__ ax4, const float4* __restrict__ ay4) {
    __shared__ unsigned int s_epoch;
    const int t = threadIdx.x;
    if (t == 0) s_epoch = atomicAdd(&g_scat_calls, 1u) / SCAT_BLOCKS;
    __syncthreads();
    const unsigned int par = s_epoch & 1u;

    if (blockIdx.x == 0 && t == 1) g_par_pub = par;   // publish for apply

    const int j = blockIdx.x * 256 + t;
    int nfirst = 0;
    if (j < N_PTS4) {
        float4 x = ax4[j];
        float4 y = ay4[j];
        nfirst += mark_point(x.x, y.x, par) ? 1 : 0;
        nfirst += mark_point(x.y, y.y, par) ? 1 : 0;
        nfirst += mark_point(x.z, y.z, par) ? 1 : 0;
        nfirst += mark_point(x.w, y.w, par) ? 1 : 0;
    }
    // warp-aggregated count: one atomic per warp
    #pragma unroll
    for (int o = 16; o > 0; o >>= 1)
        nfirst += __shfl_down_sync(0xffffffffu, nfirst, o);
    if ((t & 31) == 0 && nfirst)
        atomicAdd(&g_cnt[par], (unsigned int)nfirst);
}

// Apply: out = in * mask * scale — measured-best shape (BPT=4, MLP=4,
// __ldcs loads, __stcs stores). Mask state issued first so its L1/L2
// access overlaps the data-load issue slots. Plain L1-cached mask reads
// are safe (L1 flushed at launch boundary). Side duty: zero the OTHER
// parity's buffer for the next call.
__global__ void __launch_bounds__(256)
k_apply(const float4* __restrict__ in, float4* __restrict__ out) {
    const int t = threadIdx.x;
    const int b = blockIdx.x;
    const int tid = b * 256 + t;

    const unsigned int par = g_par_pub;               // set by this call's scatter

    // zero next call's buffer + count slot
    if (b < 8) g_mask[1u - par][b * 256 + t] = 0u;
    if (b == 8 && t == 0) g_cnt[1u - par] = 0u;

    const int m = tid & (N_M4 - 1);      // float4 index within a batch row
    const int g = tid >> 14;             // batch group (0..127)
    const long base = (long)(g * BPT) * N_M4 + m;
    const float4* p = in + base;
    float4* q = out + base;

    // mask state first (L1/L2 hits) — in flight while data loads issue
    unsigned int cnt = g_cnt[par];
    unsigned int word = g_mask[par][m >> 3];          // 4B, L1-resident

    // 4 independent read-once streaming loads (MLP=4)
    float4 v0 = __ldcs(p + 0 * N_M4);
    float4 v1 = __ldcs(p + 1 * N_M4);
    float4 v2 = __ldcs(p + 2 * N_M4);
    float4 v3 = __ldcs(p + 3 * N_M4);

    float scale = __fdividef((float)N_CELLS, (float)(N_CELLS - cnt));
    unsigned int bits = (word >> ((m & 7) * 4)) & 0xFu;

    float sx = (bits & 1u) ? 0.0f : scale;
    float sy = (bits & 2u) ? 0.0f : scale;
    float sz = (bits & 4u) ? 0.0f : scale;
    float sw = (bits & 8u) ? 0.0f : scale;

    v0.x *= sx; v0.y *= sy; v0.z *= sz; v0.w *= sw;
    v1.x *= sx; v1.y *= sy; v1.z *= sz; v1.w *= sw;
    v2.x *= sx; v2.y *= sy; v2.z *= sz; v2.w *= sw;
    v3.x *= sx; v3.y *= sy; v3.z *= sz; v3.w *= sw;

    // streaming stores: evict-first, drain to DRAM early
    __stcs(q + 0 * N_M4, v0);
    __stcs(q + 1 * N_M4, v1);
    __stcs(q + 2 * N_M4, v2);
    __stcs(q + 3 * N_M4, v3);
}

extern "C" void kernel_launch(void* const* d_in, const int* in_sizes, int n_in,
                              void* d_out, int out_size) {
    const float* input = (const float*)d_in[0];
    const float* agents_x = (const float*)d_in[1];
    const float* agents_y = (const float*)d_in[2];
    float* out = (float*)d_out;

    k_scatter<<<SCAT_BLOCKS, 256>>>((const float4*)agents_x,
                                    (const float4*)agents_y);
    k_apply<<<APPLY_BLOCKS, 256>>>((const float4*)input, (float4*)out);
}

// round 17
// speedup vs baseline: 1.0054x; 1.0054x over previous
#include <cuda_runtime.h>

#define N_COL 256
#define N_ROW 256
#define N_CELLS (N_COL * N_ROW)
#define N_WORDS (N_CELLS / 32)          // 2048 bitmask words (8 KB)
#define N_AGENT_PTS (64 * 1001)         // 64064
#define N_PTS4 (N_AGENT_PTS / 4)        // 16016
#define BATCH 512
#define N_M4 (N_CELLS / 4)              // 16384 float4s per batch row
#define BPT 4                           // batch rows per apply thread

#define SCAT_BLOCKS 63                  // ceil(16016/256)
#define APPLY_BLOCKS (N_M4 * (BATCH / BPT) / 256)   // 8192

// Parity double-buffered bitmask + counts. Call with epoch e uses buffer
// e&1, zeroed during call e-1's apply (kernel boundary publishes it).
// Zero-initialized at module load -> epoch 0 valid.
__device__ __align__(16) unsigned int g_mask[2][N_WORDS];
__device__ unsigned int g_cnt[2];
__device__ unsigned int g_par_pub;      // parity of the current call
// Monotonic scatter call counter (never reset -> graph-replay deterministic).
__device__ unsigned int g_scat_calls;

__device__ __forceinline__ bool mark_point(float x, float y, unsigned int par) {
    float fx = x * (float)N_COL;
    float fy = y * (float)N_ROW;
    float cx = floorf(fx);
    float cy = floorf(fy);
    float rx = fx - cx;
    float ry = fy - cy;
    bool in_box = (rx >= 0.25f) && (rx <= 0.75f) &&
                  (ry >= 0.25f) && (ry <= 0.75f);
    if (!in_box) return false;
    int ix = min(max((int)cx, 0), N_COL - 1);
    int iy = min(max((int)cy, 0), N_ROW - 1);
    // rot90 CCW folded in: (ix,iy) -> k = (255-iy)*256 + ix
    int k = (N_ROW - 1 - iy) * N_COL + ix;
    unsigned int bit = 1u << (k & 31);
    unsigned int old = atomicOr(&g_mask[par][k >> 5], bit);
    return !(old & bit);                // first toucher this call
}

// Scatter: 63 blocks, 4 agent points per thread via float4 loads.
// No init phase, no barrier — buffer pre-zeroed by previous apply.
__global__ void __launch_bounds__(256)
k_scatter(const float4* __restrict__ ax4, const float4* __restrict__ ay4) {
    __shared__ unsigned int s_epoch;
    const int t = threadIdx.x;
    if (t == 0) s_epoch = atomicAdd(&g_scat_calls, 1u) / SCAT_BLOCKS;
    __syncthreads();
    const unsigned int par = s_epoch & 1u;

    if (blockIdx.x == 0 && t == 1) g_par_pub = par;   // publish for apply

    const int j = blockIdx.x * 256 + t;
    int nfirst = 0;
    if (j < N_PTS4) {
        float4 x = ax4[j];
        float4 y = ay4[j];
        nfirst += mark_point(x.x, y.x, par) ? 1 : 0;
        nfirst += mark_point(x.y, y.y, par) ? 1 : 0;
        nfirst += mark_point(x.z, y.z, par) ? 1 : 0;
        nfirst += mark_point(x.w, y.w, par) ? 1 : 0;
    }
    // warp-aggregated count: one atomic per warp
    #pragma unroll
    for (int o = 16; o > 0; o >>= 1)
        nfirst += __shfl_down_sync(0xffffffffu, nfirst, o);
    if ((t & 31) == 0 && nfirst)
        atomicAdd(&g_cnt[par], (unsigned int)nfirst);
}

// Apply: out = in * mask * scale — measured-best shape (BPT=4, MLP=4,
// __ldcs loads, __stcs stores). Plain L1-cached mask reads are safe (L1 is
// flushed at launch boundary). Side duty: zero the OTHER parity's buffer.
__global__ void __launch_bounds__(256)
k_apply(const float4* __restrict__ in, float4* __restrict__ out) {
    const int t = threadIdx.x;
    const int b = blockIdx.x;
    const int tid = b * 256 + t;

    const unsigned int par = g_par_pub;               // set by this call's scatter

    // zero next call's buffer + count slot
    if (b < 8) g_mask[1u - par][b * 256 + t] = 0u;
    if (b == 8 && t == 0) g_cnt[1u - par] = 0u;

    const int m = tid & (N_M4 - 1);      // float4 index within a batch row
    const int g = tid >> 14;             // batch group (0..127)
    const long base = (long)(g * BPT) * N_M4 + m;
    const float4* p = in + base;
    float4* q = out + base;

    // 4 independent read-once streaming loads (MLP=4)
    float4 v0 = __ldcs(p + 0 * N_M4);
    float4 v1 = __ldcs(p + 1 * N_M4);
    float4 v2 = __ldcs(p + 2 * N_M4);
    float4 v3 = __ldcs(p + 3 * N_M4);

    unsigned int cnt = g_cnt[par];
    float scale = (float)N_CELLS / (float)(N_CELLS - cnt);

    unsigned int word = g_mask[par][m >> 3];          // 4B, L1-resident
    unsigned int bits = (word >> ((m & 7) * 4)) & 0xFu;

    float sx = (bits & 1u) ? 0.0f : scale;
    float sy = (bits & 2u) ? 0.0f : scale;
    float sz = (bits & 4u) ? 0.0f : scale;
    float sw = (bits & 8u) ? 0.0f : scale;

    v0.x *= sx; v0.y *= sy; v0.z *= sz; v0.w *= sw;
    v1.x *= sx; v1.y *= sy; v1.z *= sz; v1.w *= sw;
    v2.x *= sx; v2.y *= sy; v2.z *= sz; v2.w *= sw;
    v3.x *= sx; v3.y *= sy; v3.z *= sz; v3.w *= sw;

    // streaming stores: evict-first, drain to DRAM early
    __stcs(q + 0 * N_M4, v0);
    __stcs(q + 1 * N_M4, v1);
    __stcs(q + 2 * N_M4, v2);
    __stcs(q + 3 * N_M4, v3);
}

extern "C" void kernel_launch(void* const* d_in, const int* in_sizes, int n_in,
                              void* d_out, int out_size) {
    const float* input = (const float*)d_in[0];
    const float* agents_x = (const float*)d_in[1];
    const float* agents_y = (const float*)d_in[2];
    float* out = (float*)d_out;

    k_scatter<<<SCAT_BLOCKS, 256>>>((const float4*)agents_x,
                                    (const float4*)agents_y);
    k_apply<<<APPLY_BLOCKS, 256>>>((const float4*)input, (float4*)out);
}